// round 2
// baseline (speedup 1.0000x reference)
#include <cuda_runtime.h>
#include <cuda_bf16.h>

#define NSEQ   2048
#define DMODEL 1024
#define NB     4
#define MTOT   (NB * NSEQ)   // 8192 rows for QKV gemm

// -------- scratch (static device globals; allocation-free) ----------
__device__ __align__(128) float g_Q[(size_t)NB * NSEQ * DMODEL];
__device__ __align__(128) float g_K[(size_t)NB * NSEQ * DMODEL];
__device__ __align__(128) float g_V[(size_t)NB * NSEQ * DMODEL];
__device__ __align__(128) float g_S[(size_t)NB * NSEQ * NSEQ];

// ---------------------------------------------------------------
// 128x128 fp32 SGEMM tile, BK=8, 256 threads, 8x8 per-thread tile.
// BT=false: B is [K,N] row-major (NN).  BT=true: B is [N,K] row-major (NT).
// ---------------------------------------------------------------
template <bool BT>
__device__ __forceinline__ void sgemm_tile_128(
    const float* __restrict__ A, int lda,
    const float* __restrict__ B, int ldb,
    float*       __restrict__ C, int ldc,
    int m0, int n0, int kEnd, float scale)
{
    __shared__ float As[8][132];
    __shared__ float Bs[8][132];

    const int tid = threadIdx.x;
    const int ty  = tid >> 4;      // 0..15
    const int tx  = tid & 15;      // 0..15

    float acc[8][8];
#pragma unroll
    for (int i = 0; i < 8; i++)
#pragma unroll
        for (int j = 0; j < 8; j++) acc[i][j] = 0.f;

    const int aRow = tid >> 1;            // 0..127
    const int aCol = (tid & 1) << 2;      // 0 or 4
    const int bRowN = tid >> 5;           // 0..7   (NN)
    const int bColN = (tid & 31) << 2;    // 0..124 (NN)

    for (int k0 = 0; k0 < kEnd; k0 += 8) {
        // A tile [128 x 8], store transposed As[k][m]
        float4 a4 = *(const float4*)(A + (size_t)(m0 + aRow) * lda + k0 + aCol);
        As[aCol + 0][aRow] = a4.x;
        As[aCol + 1][aRow] = a4.y;
        As[aCol + 2][aRow] = a4.z;
        As[aCol + 3][aRow] = a4.w;

        if (BT) {
            // B tile [128(n) x 8(k)] from row-major [N,K]; store transposed Bs[k][n]
            float4 b4 = *(const float4*)(B + (size_t)(n0 + aRow) * ldb + k0 + aCol);
            Bs[aCol + 0][aRow] = b4.x;
            Bs[aCol + 1][aRow] = b4.y;
            Bs[aCol + 2][aRow] = b4.z;
            Bs[aCol + 3][aRow] = b4.w;
        } else {
            // B tile [8(k) x 128(n)] from row-major [K,N]; direct copy
            float4 b4 = *(const float4*)(B + (size_t)(k0 + bRowN) * ldb + n0 + bColN);
            *(float4*)&Bs[bRowN][bColN] = b4;
        }
        __syncthreads();

#pragma unroll
        for (int kk = 0; kk < 8; kk++) {
            float a[8], b[8];
            *(float4*)&a[0] = *(const float4*)&As[kk][ty * 8];
            *(float4*)&a[4] = *(const float4*)&As[kk][ty * 8 + 4];
            *(float4*)&b[0] = *(const float4*)&Bs[kk][tx * 8];
            *(float4*)&b[4] = *(const float4*)&Bs[kk][tx * 8 + 4];
#pragma unroll
            for (int i = 0; i < 8; i++)
#pragma unroll
                for (int j = 0; j < 8; j++)
                    acc[i][j] += a[i] * b[j];
        }
        __syncthreads();
    }

#pragma unroll
    for (int i = 0; i < 8; i++) {
        float* crow = C + (size_t)(m0 + ty * 8 + i) * ldc + n0 + tx * 8;
        float4 o0, o1;
        o0.x = acc[i][0] * scale; o0.y = acc[i][1] * scale;
        o0.z = acc[i][2] * scale; o0.w = acc[i][3] * scale;
        o1.x = acc[i][4] * scale; o1.y = acc[i][5] * scale;
        o1.z = acc[i][6] * scale; o1.w = acc[i][7] * scale;
        *(float4*)(crow)     = o0;
        *(float4*)(crow + 4) = o1;
    }
}

// ------------------- kernel 1: QKV projections ----------------------
// grid (DMODEL/128=8, MTOT/128=64, 3)
__global__ __launch_bounds__(256) void qkv_kernel(
    const float* __restrict__ x,
    const float* __restrict__ Wq,
    const float* __restrict__ Wk,
    const float* __restrict__ Wv)
{
    const float* W;
    float* C;
    if (blockIdx.z == 0)      { W = Wq; C = g_Q; }
    else if (blockIdx.z == 1) { W = Wk; C = g_K; }
    else                      { W = Wv; C = g_V; }
    sgemm_tile_128<false>(x, DMODEL, W, DMODEL, C, DMODEL,
                          blockIdx.y * 128, blockIdx.x * 128, DMODEL, 1.f);
}

// ------------------- kernel 2: S = Q K^T / sqrt(d) ------------------
// grid (16, 16, 4); upper-triangular blocks skipped (softmax never reads them)
__global__ __launch_bounds__(256) void scores_kernel()
{
    const int bj = blockIdx.x, bi = blockIdx.y, b = blockIdx.z;
    if (bj > bi) return;
    const float* Q  = g_Q + (size_t)b * NSEQ * DMODEL;
    const float* Km = g_K + (size_t)b * NSEQ * DMODEL;
    float*       S  = g_S + (size_t)b * NSEQ * NSEQ;
    sgemm_tile_128<true>(Q, DMODEL, Km, DMODEL, S, NSEQ,
                         bi * 128, bj * 128, DMODEL, 0.03125f);
}

// ------------------- kernel 3: causal row softmax -------------------
// one block (256 threads) per row; values kept in registers (<=8/thread)
__global__ __launch_bounds__(256) void softmax_kernel()
{
    const int row = blockIdx.x;          // 0..8191
    const int b   = row >> 11;
    const int i   = row & (NSEQ - 1);
    float* Srow = g_S + (size_t)b * NSEQ * NSEQ + (size_t)i * NSEQ;
    const int tid = threadIdx.x;

    float v[8];
    int   cnt = 0;
    float m = -1e30f;
    for (int j = tid; j <= i; j += 256) {
        v[cnt] = Srow[j];
        m = fmaxf(m, v[cnt]);
        cnt++;
    }

    __shared__ float red[8];
    __shared__ float bcast;

    // block max
#pragma unroll
    for (int o = 16; o; o >>= 1) m = fmaxf(m, __shfl_xor_sync(0xffffffffu, m, o));
    if ((tid & 31) == 0) red[tid >> 5] = m;
    __syncthreads();
    if (tid < 32) {
        float t = (tid < 8) ? red[tid] : -1e30f;
#pragma unroll
        for (int o = 4; o; o >>= 1) t = fmaxf(t, __shfl_xor_sync(0xffffffffu, t, o));
        if (tid == 0) bcast = t;
    }
    __syncthreads();
    m = bcast;

    // exp + block sum
    float s = 0.f;
    for (int t = 0; t < cnt; t++) {
        v[t] = __expf(v[t] - m);
        s += v[t];
    }
#pragma unroll
    for (int o = 16; o; o >>= 1) s += __shfl_xor_sync(0xffffffffu, s, o);
    if ((tid & 31) == 0) red[tid >> 5] = s;
    __syncthreads();
    if (tid < 32) {
        float t = (tid < 8) ? red[tid] : 0.f;
#pragma unroll
        for (int o = 4; o; o >>= 1) t += __shfl_xor_sync(0xffffffffu, t, o);
        if (tid == 0) bcast = t;
    }
    __syncthreads();
    const float inv = 1.f / bcast;

    int idx = 0;
    for (int j = tid; j <= i; j += 256) Srow[j] = v[idx++] * inv;

    // zero-fill (i, tile_end) so PV can read whole 128-wide k tiles unmasked
    const int jend = ((i >> 7) + 1) << 7;
    for (int j = i + 1 + tid; j < jend; j += 256) Srow[j] = 0.f;
}

// ------------------- kernel 4: O = P V ------------------------------
// grid (DMODEL/128=8, NSEQ/128=16, 4); causal k truncation per m-tile
__global__ __launch_bounds__(256) void pv_kernel(float* __restrict__ out)
{
    const int nj = blockIdx.x, mi = blockIdx.y, b = blockIdx.z;
    const float* S = g_S + (size_t)b * NSEQ * NSEQ;
    const float* V = g_V + (size_t)b * NSEQ * DMODEL;
    float*       O = out + (size_t)b * NSEQ * DMODEL;
    sgemm_tile_128<false>(S, NSEQ, V, DMODEL, O, DMODEL,
                          mi * 128, nj * 128, (mi + 1) * 128, 1.f);
}

// --------------------------------------------------------------------
extern "C" void kernel_launch(void* const* d_in, const int* in_sizes, int n_in,
                              void* d_out, int out_size)
{
    const float* x  = (const float*)d_in[0];
    const float* Wq = (const float*)d_in[1];
    const float* Wk = (const float*)d_in[2];
    const float* Wv = (const float*)d_in[3];
    float* out = (float*)d_out;

    qkv_kernel<<<dim3(DMODEL / 128, MTOT / 128, 3), 256>>>(x, Wq, Wk, Wv);
    scores_kernel<<<dim3(NSEQ / 128, NSEQ / 128, NB), 256>>>();
    softmax_kernel<<<dim3(MTOT), 256>>>();
    pv_kernel<<<dim3(DMODEL / 128, NSEQ / 128, NB), 256>>>(out);
}

// round 4
// speedup vs baseline: 2.7262x; 2.7262x over previous
#include <cuda_runtime.h>
#include <cuda_bf16.h>
#include <cstdint>

#define NSEQ   2048
#define DMODEL 1024
#define NB     4
#define MTOT   (NB * NSEQ)

// ---------------- static scratch (allocation-free) ------------------
__device__ __align__(128) __nv_bfloat16 g_Xh[(size_t)MTOT * DMODEL];
__device__ __align__(128) __nv_bfloat16 g_Xl[(size_t)MTOT * DMODEL];
__device__ __align__(128) __nv_bfloat16 g_Wh[3][(size_t)DMODEL * DMODEL];
__device__ __align__(128) __nv_bfloat16 g_Wl[3][(size_t)DMODEL * DMODEL];
__device__ __align__(128) __nv_bfloat16 g_Qh[(size_t)MTOT * DMODEL];
__device__ __align__(128) __nv_bfloat16 g_Ql[(size_t)MTOT * DMODEL];
__device__ __align__(128) __nv_bfloat16 g_Kh[(size_t)MTOT * DMODEL];
__device__ __align__(128) __nv_bfloat16 g_Kl[(size_t)MTOT * DMODEL];
__device__ __align__(128) __nv_bfloat16 g_Vh[(size_t)MTOT * DMODEL];
__device__ __align__(128) __nv_bfloat16 g_Vl[(size_t)MTOT * DMODEL];
__device__ __align__(128) float         g_S [(size_t)NB * NSEQ * NSEQ];
__device__ __align__(128) __nv_bfloat16 g_Ph[(size_t)NB * NSEQ * NSEQ];
__device__ __align__(128) __nv_bfloat16 g_Pl[(size_t)NB * NSEQ * NSEQ];

// ---------------- PTX helpers ---------------------------------------
#define CP16(dst_u32, src_ptr) \
    asm volatile("cp.async.cg.shared.global [%0], [%1], 16;" :: "r"(dst_u32), "l"(src_ptr))
#define CP_COMMIT()  asm volatile("cp.async.commit_group;")
#define CP_WAIT1()   asm volatile("cp.async.wait_group 1;")
#define CP_WAIT0()   asm volatile("cp.async.wait_group 0;")

#define LDSM4(r, addr) \
    asm volatile("ldmatrix.sync.aligned.m8n8.x4.shared.b16 {%0,%1,%2,%3}, [%4];" \
        : "=r"((r)[0]), "=r"((r)[1]), "=r"((r)[2]), "=r"((r)[3]) : "r"(addr))
#define LDSM2(r, addr) \
    asm volatile("ldmatrix.sync.aligned.m8n8.x2.shared.b16 {%0,%1}, [%2];" \
        : "=r"((r)[0]), "=r"((r)[1]) : "r"(addr))
#define LDSM2T(r, addr) \
    asm volatile("ldmatrix.sync.aligned.m8n8.x2.trans.shared.b16 {%0,%1}, [%2];" \
        : "=r"((r)[0]), "=r"((r)[1]) : "r"(addr))

#define MMA_BF16(c, a, b) \
    asm volatile("mma.sync.aligned.m16n8k16.row.col.f32.bf16.bf16.f32 " \
        "{%0,%1,%2,%3}, {%4,%5,%6,%7}, {%8,%9}, {%0,%1,%2,%3};" \
        : "+f"((c)[0]), "+f"((c)[1]), "+f"((c)[2]), "+f"((c)[3]) \
        : "r"((a)[0]), "r"((a)[1]), "r"((a)[2]), "r"((a)[3]), "r"((b)[0]), "r"((b)[1]))

// ---------------------------------------------------------------
// 128x128 tile, split-bf16 3-term GEMM: C = Ah*Bh + Ah*Bl + Al*Bh.
// BNK=1: B in gmem is [N,K] row-major (scores).  ldmatrix non-trans.
// BNK=0: B in gmem is [K,N] row-major (qkv, pv). ldmatrix .trans.
// cp.async double-buffered, 256 threads, warp grid 2(m) x 4(n).
// ---------------------------------------------------------------
template <int BNK>
__device__ __forceinline__ void mma_core(
    const __nv_bfloat16* __restrict__ Ah, const __nv_bfloat16* __restrict__ Al, int lda,
    const __nv_bfloat16* __restrict__ Bh, const __nv_bfloat16* __restrict__ Bl, int ldb,
    int m0, int n0, int kEnd, float acc[4][4][4])
{
    constexpr int SA  = 40;                         // A row stride (bf16)
    constexpr int SB  = BNK ? 40 : 136;             // B row stride (bf16)
    constexpr int ASZ = 128 * SA;                   // elems per A half-tile
    constexpr int BSZ = BNK ? 128 * SB : 32 * SB;   // elems per B half-tile
    constexpr int STGB = (2 * ASZ + 2 * BSZ) * 2;   // bytes per stage

    extern __shared__ char dynsm[];
    const uint32_t sbase = (uint32_t)__cvta_generic_to_shared(dynsm);

    const int tid  = threadIdx.x;
    const int lane = tid & 31;
    const int wid  = tid >> 5;
    const int wm   = wid >> 2;   // 0..1
    const int wn   = wid & 3;    // 0..3

    auto issue_copy = [&](int k0, int buf) {
        const uint32_t aH = sbase + buf * STGB;
        const uint32_t aL = aH + ASZ * 2;
        const uint32_t bH = aL + ASZ * 2;
        const uint32_t bL = bH + BSZ * 2;
#pragma unroll
        for (int rep = 0; rep < 2; rep++) {
            int c   = tid + rep * 256;
            int row = c >> 2;              // 0..127
            int cc  = c & 3;               // chunk within row (8 bf16)
            size_t go = (size_t)(m0 + row) * lda + k0 + cc * 8;
            uint32_t so = (uint32_t)(row * SA + cc * 8) * 2;
            CP16(aH + so, Ah + go);
            CP16(aL + so, Al + go);
        }
#pragma unroll
        for (int rep = 0; rep < 2; rep++) {
            int c = tid + rep * 256;
            if (BNK) {
                int row = c >> 2, cc = c & 3;
                size_t go = (size_t)(n0 + row) * ldb + k0 + cc * 8;
                uint32_t so = (uint32_t)(row * SB + cc * 8) * 2;
                CP16(bH + so, Bh + go);
                CP16(bL + so, Bl + go);
            } else {
                int row = c >> 4, cc = c & 15;
                size_t go = (size_t)(k0 + row) * ldb + n0 + cc * 8;
                uint32_t so = (uint32_t)(row * SB + cc * 8) * 2;
                CP16(bH + so, Bh + go);
                CP16(bL + so, Bl + go);
            }
        }
    };

    issue_copy(0, 0);
    CP_COMMIT();

    int buf = 0;
    for (int k0 = 0; k0 < kEnd; k0 += 32) {
        const bool nxt = (k0 + 32) < kEnd;
        if (nxt) issue_copy(k0 + 32, buf ^ 1);
        CP_COMMIT();
        if (nxt) CP_WAIT1(); else CP_WAIT0();
        __syncthreads();

        const uint32_t aHb = sbase + buf * STGB;
        const uint32_t aLb = aHb + ASZ * 2;
        const uint32_t bHb = aLb + ASZ * 2;
        const uint32_t bLb = bHb + BSZ * 2;

#pragma unroll
        for (int ks = 0; ks < 32; ks += 16) {
            uint32_t aHf[4][4], aLf[4][4], bHf[4][2], bLf[4][2];

            // A fragments (x4): rows m, cols k
            {
                int row = wm * 64 + (lane & 15);
                int col = ks + ((lane >> 4) << 3);
#pragma unroll
                for (int im = 0; im < 4; im++) {
                    uint32_t off = (uint32_t)((row + im * 16) * SA + col) * 2;
                    LDSM4(aHf[im], aHb + off);
                    LDSM4(aLf[im], aLb + off);
                }
            }
            // B fragments (x2)
            if (BNK) {
                int r  = wn * 32 + (lane & 7);
                int col = ks + (lane & 8);
#pragma unroll
                for (int jn = 0; jn < 4; jn++) {
                    uint32_t off = (uint32_t)((r + jn * 8) * SB + col) * 2;
                    LDSM2(bHf[jn], bHb + off);
                    LDSM2(bLf[jn], bLb + off);
                }
            } else {
                int r = ks + (lane & 15);
#pragma unroll
                for (int jn = 0; jn < 4; jn++) {
                    int cgl = wn * 32 + jn * 8;
                    uint32_t off = (uint32_t)(r * SB + cgl) * 2;
                    LDSM2T(bHf[jn], bHb + off);
                    LDSM2T(bLf[jn], bLb + off);
                }
            }

#pragma unroll
            for (int im = 0; im < 4; im++)
#pragma unroll
                for (int jn = 0; jn < 4; jn++)
                    MMA_BF16(acc[im][jn], aHf[im], bHf[jn]);
#pragma unroll
            for (int im = 0; im < 4; im++)
#pragma unroll
                for (int jn = 0; jn < 4; jn++)
                    MMA_BF16(acc[im][jn], aHf[im], bLf[jn]);
#pragma unroll
            for (int im = 0; im < 4; im++)
#pragma unroll
                for (int jn = 0; jn < 4; jn++)
                    MMA_BF16(acc[im][jn], aLf[im], bHf[jn]);
        }
        __syncthreads();
        buf ^= 1;
    }
}

// accumulator element -> global (row, col) helper data
// c0: (qr, qc)  c1: (qr, qc+1)  c2: (qr+8, qc)  c3: (qr+8, qc+1)

__device__ __forceinline__ __nv_bfloat162 split_hi2(float v0, float v1,
                                                    __nv_bfloat162& lo2)
{
    __nv_bfloat16 h0 = __float2bfloat16(v0);
    __nv_bfloat16 h1 = __float2bfloat16(v1);
    __nv_bfloat16 l0 = __float2bfloat16(v0 - __bfloat162float(h0));
    __nv_bfloat16 l1 = __float2bfloat16(v1 - __bfloat162float(h1));
    lo2 = __nv_bfloat162(l0, l1);
    return __nv_bfloat162(h0, h1);
}

// ------------------- split prep kernels -----------------------------
__global__ __launch_bounds__(256) void split_x_kernel(const float* __restrict__ src)
{
    const size_t n = (size_t)MTOT * DMODEL;
    for (size_t i = blockIdx.x * 256 + threadIdx.x; i < n; i += (size_t)gridDim.x * 256) {
        float v = src[i];
        __nv_bfloat16 h = __float2bfloat16(v);
        g_Xh[i] = h;
        g_Xl[i] = __float2bfloat16(v - __bfloat162float(h));
    }
}
__global__ __launch_bounds__(256) void split_w_kernel(const float* __restrict__ src, int which)
{
    const size_t n = (size_t)DMODEL * DMODEL;
    for (size_t i = blockIdx.x * 256 + threadIdx.x; i < n; i += (size_t)gridDim.x * 256) {
        float v = src[i];
        __nv_bfloat16 h = __float2bfloat16(v);
        g_Wh[which][i] = h;
        g_Wl[which][i] = __float2bfloat16(v - __bfloat162float(h));
    }
}

// ------------------- kernel 1: QKV projections ----------------------
// grid (8, 64, 3)
__global__ __launch_bounds__(256) void qkv_kernel()
{
    float acc[4][4][4];
#pragma unroll
    for (int i = 0; i < 4; i++)
#pragma unroll
        for (int j = 0; j < 4; j++)
#pragma unroll
            for (int k = 0; k < 4; k++) acc[i][j][k] = 0.f;

    const int z  = blockIdx.z;
    const int m0 = blockIdx.y * 128;
    const int n0 = blockIdx.x * 128;

    mma_core<0>(g_Xh, g_Xl, DMODEL, g_Wh[z], g_Wl[z], DMODEL, m0, n0, DMODEL, acc);

    __nv_bfloat16* OH = (z == 0) ? g_Qh : (z == 1) ? g_Kh : g_Vh;
    __nv_bfloat16* OL = (z == 0) ? g_Ql : (z == 1) ? g_Kl : g_Vl;

    const int lane = threadIdx.x & 31;
    const int wid  = threadIdx.x >> 5;
    const int wm = wid >> 2, wn = wid & 3;
    const int qr = lane >> 2, qc = (lane & 3) << 1;
#pragma unroll
    for (int im = 0; im < 4; im++)
#pragma unroll
        for (int jn = 0; jn < 4; jn++) {
            int row = m0 + wm * 64 + im * 16 + qr;
            int col = n0 + wn * 32 + jn * 8 + qc;
            __nv_bfloat162 lo2, hi2;
            hi2 = split_hi2(acc[im][jn][0], acc[im][jn][1], lo2);
            *(__nv_bfloat162*)&OH[(size_t)row * DMODEL + col] = hi2;
            *(__nv_bfloat162*)&OL[(size_t)row * DMODEL + col] = lo2;
            hi2 = split_hi2(acc[im][jn][2], acc[im][jn][3], lo2);
            *(__nv_bfloat162*)&OH[(size_t)(row + 8) * DMODEL + col] = hi2;
            *(__nv_bfloat162*)&OL[(size_t)(row + 8) * DMODEL + col] = lo2;
        }
}

// ------------------- kernel 2: S = Q K^T / 32 -----------------------
// grid (16, 16, 4); strictly-upper blocks skipped
__global__ __launch_bounds__(256) void scores_kernel()
{
    const int bj = blockIdx.x, bi = blockIdx.y, b = blockIdx.z;
    if (bj > bi) return;

    float acc[4][4][4];
#pragma unroll
    for (int i = 0; i < 4; i++)
#pragma unroll
        for (int j = 0; j < 4; j++)
#pragma unroll
            for (int k = 0; k < 4; k++) acc[i][j][k] = 0.f;

    const size_t qo = (size_t)b * NSEQ * DMODEL;
    const int m0 = bi * 128, n0 = bj * 128;

    mma_core<1>(g_Qh + qo, g_Ql + qo, DMODEL, g_Kh + qo, g_Kl + qo, DMODEL,
                m0, n0, DMODEL, acc);

    float* S = g_S + (size_t)b * NSEQ * NSEQ;
    const int lane = threadIdx.x & 31;
    const int wid  = threadIdx.x >> 5;
    const int wm = wid >> 2, wn = wid & 3;
    const int qr = lane >> 2, qc = (lane & 3) << 1;
#pragma unroll
    for (int im = 0; im < 4; im++)
#pragma unroll
        for (int jn = 0; jn < 4; jn++) {
            int row = m0 + wm * 64 + im * 16 + qr;
            int col = n0 + wn * 32 + jn * 8 + qc;
            float2 v0 = make_float2(acc[im][jn][0] * 0.03125f, acc[im][jn][1] * 0.03125f);
            float2 v1 = make_float2(acc[im][jn][2] * 0.03125f, acc[im][jn][3] * 0.03125f);
            *(float2*)&S[(size_t)row * NSEQ + col]       = v0;
            *(float2*)&S[(size_t)(row + 8) * NSEQ + col] = v1;
        }
}

// ------------------- kernel 3: causal softmax -> split P ------------
__global__ __launch_bounds__(256) void softmax_kernel()
{
    const int row = blockIdx.x;
    const int b   = row >> 11;
    const int i   = row & (NSEQ - 1);
    const float* Srow = g_S + (size_t)b * NSEQ * NSEQ + (size_t)i * NSEQ;
    __nv_bfloat16* Ph = g_Ph + (size_t)b * NSEQ * NSEQ + (size_t)i * NSEQ;
    __nv_bfloat16* Pl = g_Pl + (size_t)b * NSEQ * NSEQ + (size_t)i * NSEQ;
    const int tid = threadIdx.x;

    float v[8];
    int   cnt = 0;
    float m = -1e30f;
    for (int j = tid; j <= i; j += 256) {
        v[cnt] = Srow[j];
        m = fmaxf(m, v[cnt]);
        cnt++;
    }

    __shared__ float red[8];
    __shared__ float bcast;

#pragma unroll
    for (int o = 16; o; o >>= 1) m = fmaxf(m, __shfl_xor_sync(0xffffffffu, m, o));
    if ((tid & 31) == 0) red[tid >> 5] = m;
    __syncthreads();
    if (tid < 32) {
        float t = (tid < 8) ? red[tid] : -1e30f;
#pragma unroll
        for (int o = 4; o; o >>= 1) t = fmaxf(t, __shfl_xor_sync(0xffffffffu, t, o));
        if (tid == 0) bcast = t;
    }
    __syncthreads();
    m = bcast;

    float s = 0.f;
    for (int t = 0; t < cnt; t++) {
        v[t] = __expf(v[t] - m);
        s += v[t];
    }
#pragma unroll
    for (int o = 16; o; o >>= 1) s += __shfl_xor_sync(0xffffffffu, s, o);
    if ((tid & 31) == 0) red[tid >> 5] = s;
    __syncthreads();
    if (tid < 32) {
        float t = (tid < 8) ? red[tid] : 0.f;
#pragma unroll
        for (int o = 4; o; o >>= 1) t += __shfl_xor_sync(0xffffffffu, t, o);
        if (tid == 0) bcast = t;
    }
    __syncthreads();
    const float inv = 1.f / bcast;

    int idx = 0;
    for (int j = tid; j <= i; j += 256) {
        float p = v[idx++] * inv;
        __nv_bfloat16 h = __float2bfloat16(p);
        Ph[j] = h;
        Pl[j] = __float2bfloat16(p - __bfloat162float(h));
    }
    const int jend = ((i >> 7) + 1) << 7;
    for (int j = i + 1 + tid; j < jend; j += 256) {
        Ph[j] = __float2bfloat16(0.f);
        Pl[j] = __float2bfloat16(0.f);
    }
}

// ------------------- kernel 4: O = P V ------------------------------
// grid (8, 16, 4); causal k truncation
__global__ __launch_bounds__(256) void pv_kernel(float* __restrict__ out)
{
    float acc[4][4][4];
#pragma unroll
    for (int i = 0; i < 4; i++)
#pragma unroll
        for (int j = 0; j < 4; j++)
#pragma unroll
            for (int k = 0; k < 4; k++) acc[i][j][k] = 0.f;

    const int nj = blockIdx.x, mi = blockIdx.y, b = blockIdx.z;
    const size_t po = (size_t)b * NSEQ * NSEQ;
    const size_t vo = (size_t)b * NSEQ * DMODEL;
    const int m0 = mi * 128, n0 = nj * 128;

    mma_core<0>(g_Ph + po, g_Pl + po, NSEQ, g_Vh + vo, g_Vl + vo, DMODEL,
                m0, n0, (mi + 1) * 128, acc);

    float* O = out + vo;
    const int lane = threadIdx.x & 31;
    const int wid  = threadIdx.x >> 5;
    const int wm = wid >> 2, wn = wid & 3;
    const int qr = lane >> 2, qc = (lane & 3) << 1;
#pragma unroll
    for (int im = 0; im < 4; im++)
#pragma unroll
        for (int jn = 0; jn < 4; jn++) {
            int row = m0 + wm * 64 + im * 16 + qr;
            int col = n0 + wn * 32 + jn * 8 + qc;
            *(float2*)&O[(size_t)row * DMODEL + col] =
                make_float2(acc[im][jn][0], acc[im][jn][1]);
            *(float2*)&O[(size_t)(row + 8) * DMODEL + col] =
                make_float2(acc[im][jn][2], acc[im][jn][3]);
        }
}

// --------------------------------------------------------------------
extern "C" void kernel_launch(void* const* d_in, const int* in_sizes, int n_in,
                              void* d_out, int out_size)
{
    const float* x  = (const float*)d_in[0];
    const float* Wq = (const float*)d_in[1];
    const float* Wk = (const float*)d_in[2];
    const float* Wv = (const float*)d_in[3];
    float* out = (float*)d_out;

    // smem bytes per stage: A = 2*128*40, B(BNK0) = 2*32*136, B(BNK1) = 2*128*40 (bf16)
    const int smemNN = 2 * (2 * 128 * 40 + 2 * 32 * 136) * 2;   // 75776
    const int smemNT = 2 * (2 * 128 * 40 + 2 * 128 * 40) * 2;   // 81920
    cudaFuncSetAttribute(qkv_kernel,    cudaFuncAttributeMaxDynamicSharedMemorySize, smemNN);
    cudaFuncSetAttribute(scores_kernel, cudaFuncAttributeMaxDynamicSharedMemorySize, smemNT);
    cudaFuncSetAttribute(pv_kernel,     cudaFuncAttributeMaxDynamicSharedMemorySize, smemNN);

    split_x_kernel<<<4096, 256>>>(x);
    split_w_kernel<<<1024, 256>>>(Wq, 0);
    split_w_kernel<<<1024, 256>>>(Wk, 1);
    split_w_kernel<<<1024, 256>>>(Wv, 2);

    qkv_kernel<<<dim3(DMODEL / 128, MTOT / 128, 3), 256, smemNN>>>();
    scores_kernel<<<dim3(NSEQ / 128, NSEQ / 128, NB), 256, smemNT>>>();
    softmax_kernel<<<dim3(MTOT), 256>>>();
    pv_kernel<<<dim3(DMODEL / 128, NSEQ / 128, NB), 256, smemNN>>>(out);
}